// round 3
// baseline (speedup 1.0000x reference)
#include <cuda_runtime.h>

#define BB   8
#define HH   384
#define WW   384
#define CIN  8
#define OCH  18
#define TW   32     // tile width  (8 threads x * 4 px)
#define TH   16     // tile height (16 threads y)
#define SW   36     // padded smem row (34 used + 2 pad, 16B alignment)
#define SH   18

typedef unsigned long long ull;

__device__ __forceinline__ ull pk2(float lo, float hi) {
    ull r; asm("mov.b64 %0, {%1, %2};" : "=l"(r) : "f"(lo), "f"(hi)); return r;
}
__device__ __forceinline__ ull f2fma(ull a, ull b, ull c) {
    ull d; asm("fma.rn.f32x2 %0, %1, %2, %3;" : "=l"(d) : "l"(a), "l"(b), "l"(c)); return d;
}
__device__ __forceinline__ float2 upk2(ull v) {
    float2 f; asm("mov.b64 {%0, %1}, %2;" : "=f"(f.x), "=f"(f.y) : "l"(v)); return f;
}

// ---- smem layout (bytes) ----
#define OFF_X    0
#define SZ_X     (CIN * SH * SW * 4)            // 20736
#define OFF_WK   (OFF_X + SZ_X)                 // 20736 (16B aligned)
#define SZ_WK    (9 * CIN * 9 * 16)             // 10368: [k][ci][ky][kx] -> ulonglong2 {splat(w_y), splat(w_x)}
#define OFF_DW   (OFF_WK + SZ_WK)               // 31104
#define SZ_DW    (27 * 16)                      // 432
#define OFF_B    (OFF_DW + SZ_DW)               // 31536
#define SZ_B     (OCH * 4)                      // 72
#define SMEM_TOTAL (OFF_B + SZ_B)               // 31608

// Bilinear sample (3 channels, zero pad) + weighted accumulate.
__device__ __forceinline__ void sample_px(const float* __restrict__ p0,
                                          float py, float px,
                                          const float4* __restrict__ dwk, // &s_dw4[k], stride 9
                                          float& a0, float& a1, float& a2) {
    int y0 = __float2int_rd(py);
    int x0 = __float2int_rd(px);
    float wy = py - (float)y0;
    float wx = px - (float)x0;
    bool y0v = ((unsigned)y0 < (unsigned)HH);
    bool y1v = ((unsigned)(y0 + 1) < (unsigned)HH);
    bool x0v = ((unsigned)x0 < (unsigned)WW);
    bool x1v = ((unsigned)(x0 + 1) < (unsigned)WW);
    float iy = 1.f - wy, ix = 1.f - wx;
    float w00 = iy * ix, w01 = iy * wx, w10 = wy * ix, w11 = wy * wx;
    int i00 = y0 * WW + x0;                      // 32-bit index math
#pragma unroll
    for (int c = 0; c < 3; ++c) {
        const float* p = p0 + c * (HH * WW);
        float v00 = (y0v && x0v) ? __ldg(p + i00)          : 0.f;
        float v01 = (y0v && x1v) ? __ldg(p + i00 + 1)      : 0.f;
        float v10 = (y1v && x0v) ? __ldg(p + i00 + WW)     : 0.f;
        float v11 = (y1v && x1v) ? __ldg(p + i00 + WW + 1) : 0.f;
        float s = fmaf(w00, v00, fmaf(w01, v01, fmaf(w10, v10, w11 * v11)));
        float4 dw = dwk[c * 9];
        a0 = fmaf(dw.x, s, a0);
        a1 = fmaf(dw.y, s, a1);
        a2 = fmaf(dw.z, s, a2);
    }
}

__global__ __launch_bounds__(128, 6)
void guided_cnn_fused(const float* __restrict__ pf,
                      const float* __restrict__ cf,
                      const float* __restrict__ mv,
                      const float* __restrict__ ow,   // (18,8,3,3)
                      const float* __restrict__ ob,   // (18,)
                      const float* __restrict__ dw,   // (3,3,3,3)
                      float* __restrict__ out) {
    extern __shared__ char smem[];
    float*      s_x   = (float*)(smem + OFF_X);        // [CIN][SH][SW]
    ulonglong2* s_wk  = (ulonglong2*)(smem + OFF_WK);  // [k][ci][ky][kx]
    float4*     s_dw4 = (float4*)(smem + OFF_DW);      // [c*9+k]
    float*      s_b   = (float*)(smem + OFF_B);

    const int tx  = threadIdx.x;            // 0..7
    const int ty  = threadIdx.y;            // 0..15
    const int tid = ty * 8 + tx;
    const int b   = blockIdx.z;
    const int h0  = blockIdx.y * TH;
    const int w0  = blockIdx.x * TW;

    // ---- stage conv weights: per tap k, per (ci,ky,kx): {splat(w[2k]), splat(w[2k+1])} ----
    for (int i = tid; i < 9 * CIN * 9; i += 128) {
        int r  = i % 9;           // ky*3+kx
        int ci = (i / 9) % CIN;
        int k  = i / (9 * CIN);
        float w0v = __ldg(ow + ((2 * k)     * CIN + ci) * 9 + r);
        float w1v = __ldg(ow + ((2 * k + 1) * CIN + ci) * 9 + r);
        ulonglong2 e; e.x = pk2(w0v, w0v); e.y = pk2(w1v, w1v);
        s_wk[i] = e;
    }
    for (int i = tid; i < 27; i += 128) {
        int c = i / 9, k = i % 9;
        s_dw4[i] = make_float4(__ldg(dw + 0 * 27 + c * 9 + k),
                               __ldg(dw + 1 * 27 + c * 9 + k),
                               __ldg(dw + 2 * 27 + c * 9 + k), 0.f);
    }
    if (tid < OCH) s_b[tid] = __ldg(ob + tid);

    // ---- stage input tile (8 ch, halo 1) ----
    for (int i = tid; i < CIN * SH * SW; i += 128) {
        int c  = i % SW;
        int r  = (i / SW) % SH;
        int ch = i / (SW * SH);
        int gh = h0 - 1 + r;
        int gw = w0 - 1 + c;
        float v = 0.f;
        if ((unsigned)gh < (unsigned)HH && (unsigned)gw < (unsigned)WW) {
            const float* src;
            if (ch < 3)      src = pf + (((long)b * 3 + ch)     * HH + gh) * WW + gw;
            else if (ch < 6) src = cf + (((long)b * 3 + ch - 3) * HH + gh) * WW + gw;
            else             src = mv + (((long)b * 2 + ch - 6) * HH + gh) * WW + gw;
            v = __ldg(src);
        }
        s_x[i] = v;
    }
    __syncthreads();

    const int h   = h0 + ty;
    const int wpx = w0 + 4 * tx;
    const float* p0 = pf + (long)b * 3 * HH * WW;   // plane 0; planes 1,2 at +HH*WW

    float a0[4] = {0, 0, 0, 0};
    float a1[4] = {0, 0, 0, 0};
    float a2[4] = {0, 0, 0, 0};

#pragma unroll 1
    for (int k = 0; k < 9; ++k) {
        // ---- offset conv for this tap: ch 2k (y), 2k+1 (x), 4 pixels ----
        float by0 = s_b[2 * k];
        float bx0 = s_b[2 * k + 1];
        ull yA = pk2(by0, by0), yB = yA;
        ull xA = pk2(bx0, bx0), xB = xA;

        const ulonglong2* wkbase = s_wk + k * (CIN * 9);
#pragma unroll
        for (int ci = 0; ci < CIN; ++ci) {
#pragma unroll
            for (int ky = 0; ky < 3; ++ky) {
                const float* rp = s_x + (ci * SH + (ty + ky)) * SW + 4 * tx;
                float4 q  = *reinterpret_cast<const float4*>(rp);
                float2 r2 = *reinterpret_cast<const float2*>(rp + 4);
                ull u01 = pk2(q.x, q.y);
                ull u12 = pk2(q.y, q.z);
                ull u23 = pk2(q.z, q.w);
                ull u34 = pk2(q.w, r2.x);
                ull u45 = pk2(r2.x, r2.y);
                const ulonglong2* wb = wkbase + (ci * 3 + ky) * 3;
                ulonglong2 wk0 = wb[0];
                ulonglong2 wk1 = wb[1];
                ulonglong2 wk2 = wb[2];
                yA = f2fma(u01, wk0.x, yA);  yB = f2fma(u23, wk0.x, yB);
                xA = f2fma(u01, wk0.y, xA);  xB = f2fma(u23, wk0.y, xB);
                yA = f2fma(u12, wk1.x, yA);  yB = f2fma(u34, wk1.x, yB);
                xA = f2fma(u12, wk1.y, xA);  xB = f2fma(u34, wk1.y, xB);
                yA = f2fma(u23, wk2.x, yA);  yB = f2fma(u45, wk2.x, yB);
                xA = f2fma(u23, wk2.y, xA);  xB = f2fma(u45, wk2.y, xB);
            }
        }

        // ---- sample this tap for 4 pixels ----
        const int kyi = k / 3, kxi = k % 3;
        float2 oyA = upk2(yA), oxA = upk2(xA);
        float2 oyB = upk2(yB), oxB = upk2(xB);
        const float by = (float)(kyi + h - 1);
        const float bx = (float)(kxi + wpx - 1);
        const float4* dwk = s_dw4 + k;
        sample_px(p0, oyA.x + by, oxA.x + bx,       dwk, a0[0], a1[0], a2[0]);
        sample_px(p0, oyA.y + by, oxA.y + bx + 1.f, dwk, a0[1], a1[1], a2[1]);
        sample_px(p0, oyB.x + by, oxB.x + bx + 2.f, dwk, a0[2], a1[2], a2[2]);
        sample_px(p0, oyB.y + by, oxB.y + bx + 3.f, dwk, a0[3], a1[3], a2[3]);
    }

    float* ob0 = out + (((long)b * 3 + 0) * HH + h) * WW + wpx;
    float* ob1 = out + (((long)b * 3 + 1) * HH + h) * WW + wpx;
    float* ob2 = out + (((long)b * 3 + 2) * HH + h) * WW + wpx;
    *reinterpret_cast<float4*>(ob0) = make_float4(a0[0], a0[1], a0[2], a0[3]);
    *reinterpret_cast<float4*>(ob1) = make_float4(a1[0], a1[1], a1[2], a1[3]);
    *reinterpret_cast<float4*>(ob2) = make_float4(a2[0], a2[1], a2[2], a2[3]);
}

extern "C" void kernel_launch(void* const* d_in, const int* in_sizes, int n_in,
                              void* d_out, int out_size) {
    const float* pf = (const float*)d_in[0];
    const float* cf = (const float*)d_in[1];
    const float* mv = (const float*)d_in[2];
    const float* ow = (const float*)d_in[3];
    const float* ob = (const float*)d_in[4];
    const float* dw = (const float*)d_in[5];
    float* out = (float*)d_out;

    cudaFuncSetAttribute(guided_cnn_fused,
                         cudaFuncAttributeMaxDynamicSharedMemorySize, SMEM_TOTAL);

    dim3 blk(8, 16);
    dim3 grd(WW / TW, HH / TH, BB);   // 12 x 24 x 8 = 2304
    guided_cnn_fused<<<grd, blk, SMEM_TOTAL>>>(pf, cf, mv, ow, ob, dw, out);
}